// round 10
// baseline (speedup 1.0000x reference)
#include <cuda_runtime.h>
#include <cstdint>

// Problem sizes (fixed by reference)
#define S_DIM  1024
#define P_DIM  8
#define N_PTS  8192            // S*P flattened colors

// NOTE: the reference sorts palette rows per column before the softmin, but
// the final loss is a MEAN over all queries -> permutation-invariant. The
// sort is a no-op on the output scalar and is omitted entirely.

#define BLK    256             // 8 warps/block
#define GX     32              // query blocks: 32*256 = 8192 queries
#define NCH    18              // key chunks; grid 32 x 18 = 576 blocks (~4/SM)
#define MC     456             // ceil(8192/18); last chunk = 440

// Coordinates pre-scaled by LG2E so u = sqrt(s') = log2(e)*dist and
// exp(-dist) = ex2(-u): zero extra FMA for the exponent argument.
#define LG2E  1.4426950408889634f
#define ILG2E 0.6931471805599453f

// Per-query accumulator {sum_w, accx, accy, accz}. Zero at module load;
// the final kernel re-zeroes it after consuming, so every graph replay
// (and the correctness call) sees a clean buffer. No memset node needed.
__device__ float4 g_acc[N_PTS];

__device__ __forceinline__ float sqrt_ap(float x) {
    float r; asm("sqrt.approx.f32 %0, %1;" : "=f"(r) : "f"(x)); return r;
}
__device__ __forceinline__ float ex2_ap(float x) {
    float r; asm("ex2.approx.f32 %0, %1;" : "=f"(r) : "f"(x)); return r;
}

// Clipped, LG2E-scaled palette color for query q.
__device__ __forceinline__ float4 query_quad(const float* __restrict__ pallet, int q) {
    float x = fminf(fmaxf(pallet[3 * q]     * 0.5f, 0.f), 1.f);
    float y = fminf(fmaxf(pallet[3 * q + 1] * 0.5f, 0.f), 1.f);
    float z = fminf(fmaxf(pallet[3 * q + 2] * 0.5f, 0.f), 1.f);
    float ax = x * LG2E, ay = y * LG2E, az = z * LG2E;
    return make_float4(ax, ay, az, ax * ax + ay * ay + az * az);
}

// ---------------------------------------------------------------------------
// Phase 1: 8192x8192 softmin sweep. Scalar, 1 query/thread; per key:
// 4 FMA-class (dot via norm trick) + 4 FMA (acc) + 2 MUFU (sqrt, ex2(-u)).
// fma & xu pipes co-saturated at the SIMT floor. grid (32, 18), BLK=256.
// Chunk partials go straight into g_acc via float atomics (18 adds/query
// total -- no measurable contention), eliminating the scratch round-trip.
// ---------------------------------------------------------------------------
__global__ void __launch_bounds__(BLK, 4) softmin_kernel(const float* __restrict__ pallet,
                                                         const float* __restrict__ comp) {
    __shared__ float4 sb[MC];    // {|B|^2, -2Bx, -2By, -2Bz} per key

    const int m0 = blockIdx.y * MC;
    const int mc = min(MC, N_PTS - m0);
    for (int i = threadIdx.x; i < mc; i += BLK) {
        const int m = m0 + i;
        float bx = comp[3 * m] * LG2E, by = comp[3 * m + 1] * LG2E, bz = comp[3 * m + 2] * LG2E;
        sb[i] = make_float4(bx * bx + by * by + bz * bz, -2.f * bx, -2.f * by, -2.f * bz);
    }

    const int q = blockIdx.x * BLK + threadIdx.x;
    const float4 a = query_quad(pallet, q);
    const float Ax = a.x, Ay = a.y, Az = a.z, A2 = a.w;
    float sw = 0.f, cx = 0.f, cy = 0.f, cz = 0.f;

    __syncthreads();

#pragma unroll 4
    for (int i = 0; i < mc; i++) {
        const float4 b = sb[i];
        // s' = |A|^2 + |B|^2 - 2 A.B  (= log2e^2 * |a-b|^2)
        float s = fmaf(b.y, Ax, fmaf(b.z, Ay, fmaf(b.w, Az, b.x + A2)));
        // u = log2e * dist; w = 2^(-u) = exp(-dist). |.| and neg fold into MUFU.
        float w = ex2_ap(-sqrt_ap(fabsf(s)));
        sw += w;
        cx = fmaf(w, b.y, cx);   // accumulates w*(-2*LG2E*bx) etc.
        cy = fmaf(w, b.z, cy);
        cz = fmaf(w, b.w, cz);
    }

    float* dst = (float*)&g_acc[q];
    atomicAdd(dst + 0, sw);
    atomicAdd(dst + 1, cx);
    atomicAdd(dst + 2, cy);
    atomicAdd(dst + 3, cz);
}

// ---------------------------------------------------------------------------
// Phase 2: single-block finalize. 1024 threads x 8 queries: read g_acc
// (128KB, L2-resident from the atomics), compute closest + MSE term,
// re-zero g_acc for the next replay, block-reduce, store the scalar out.
// No atomics on out, no memset nodes anywhere.
// ---------------------------------------------------------------------------
#define FBLK 1024
__global__ void __launch_bounds__(FBLK) finalize_kernel(const float* __restrict__ pallet,
                                                        float* __restrict__ out) {
    const int t = threadIdx.x;
    float local = 0.f;

#pragma unroll
    for (int k = 0; k < N_PTS / FBLK; k++) {
        const int q = k * FBLK + t;
        float4 v = g_acc[q];
        g_acc[q] = make_float4(0.f, 0.f, 0.f, 0.f);   // reset for next replay

        // closest_c = acc_c / (-2 * LG2E * sum_w)   (acc holds w * -2*LG2E*b)
        const float inv = -1.f / (2.f * LG2E * v.x);
        float clx = v.y * inv, cly = v.z * inv, clz = v.w * inv;

        float4 a = query_quad(pallet, q);             // LG2E-scaled
        float ex = a.x * ILG2E - clx;
        float ey = a.y * ILG2E - cly;
        float ez = a.z * ILG2E - clz;
        local += ex * ex + ey * ey + ez * ez;
    }

    // block reduction over 1024 threads
    __shared__ float red[FBLK / 32];
    for (int off = 16; off > 0; off >>= 1)
        local += __shfl_down_sync(0xFFFFFFFFu, local, off);
    const int lane = t & 31, wid = t >> 5;
    if (lane == 0) red[wid] = local;
    __syncthreads();
    if (wid == 0) {
        local = (lane < FBLK / 32) ? red[lane] : 0.f;
        for (int off = 16; off > 0; off >>= 1)
            local += __shfl_down_sync(0xFFFFFFFFu, local, off);
        if (lane == 0)
            out[0] = local * (1.f / (float)(N_PTS * 3));
    }
}

// ---------------------------------------------------------------------------
extern "C" void kernel_launch(void* const* d_in, const int* in_sizes, int n_in,
                              void* d_out, int out_size) {
    const float* pallet = (const float*)d_in[0];
    const float* comp   = (const float*)d_in[1];
    float* out = (float*)d_out;

    softmin_kernel<<<dim3(GX, NCH), BLK>>>(pallet, comp);
    finalize_kernel<<<1, FBLK>>>(pallet, out);
}

// round 11
// speedup vs baseline: 1.1193x; 1.1193x over previous
#include <cuda_runtime.h>
#include <cstdint>

// Problem sizes (fixed by reference)
#define S_DIM  1024
#define P_DIM  8
#define N_PTS  8192            // S*P flattened colors

// NOTE: the reference sorts palette rows per column before the softmin, but
// the final loss is a MEAN over all queries -> permutation-invariant. The
// sort is a no-op on the output scalar and is omitted entirely.

#define Q_PER_THREAD 2         // 1 packed pair per thread
#define BLK          256       // 8 warps/block
#define NCH          37        // key chunks; grid 16 x 37 = 592 = 4 blocks/SM
                               // -> 32 warps/SM = 8 warps/SMSP
#define MC           222       // ceil(8192/37); last chunk = 200

// Coordinates pre-scaled by LG2E so u = sqrt(s') = log2(e)*dist and
// exp(-dist) = ex2(-u): zero extra FMA for the exponent argument.
#define LG2E  1.4426950408889634f
#define ILG2E 0.6931471805599453f

// Static device scratch (no allocations allowed)
__device__ float4 g_scratch[NCH * N_PTS];    // per-chunk partials {sum_w, accx, accy, accz}

// ---- packed f32x2 helpers -------------------------------------------------
union f2u { float2 f; unsigned long long u; };
__device__ __forceinline__ float2 ffma2(float2 a, float2 b, float2 c) {
    f2u A, B, C, D; A.f = a; B.f = b; C.f = c;
    asm("fma.rn.f32x2 %0, %1, %2, %3;" : "=l"(D.u) : "l"(A.u), "l"(B.u), "l"(C.u));
    return D.f;
}
__device__ __forceinline__ float2 fadd2(float2 a, float2 b) {
    f2u A, B, D; A.f = a; B.f = b;
    asm("add.rn.f32x2 %0, %1, %2;" : "=l"(D.u) : "l"(A.u), "l"(B.u));
    return D.f;
}
__device__ __forceinline__ float sqrt_ap(float x) {
    float r; asm("sqrt.approx.f32 %0, %1;" : "=f"(r) : "f"(x)); return r;
}
__device__ __forceinline__ float ex2_ap(float x) {
    float r; asm("ex2.approx.f32 %0, %1;" : "=f"(r) : "f"(x)); return r;
}

// Clipped, LG2E-scaled palette color for query q.
__device__ __forceinline__ float4 query_quad(const float* __restrict__ pallet, int q) {
    float x = fminf(fmaxf(pallet[3 * q]     * 0.5f, 0.f), 1.f);
    float y = fminf(fmaxf(pallet[3 * q + 1] * 0.5f, 0.f), 1.f);
    float z = fminf(fmaxf(pallet[3 * q + 2] * 0.5f, 0.f), 1.f);
    float ax = x * LG2E, ay = y * LG2E, az = z * LG2E;
    return make_float4(ax, ay, az, ax * ax + ay * ay + az * az);
}

// ---------------------------------------------------------------------------
// Phase 1: 8192x8192 softmin sweep (identical to the round-9 best: pure MUFU
// path, fma+xu pipes co-saturated at the SIMT floor). grid (16, 37), BLK=256,
// 2 queries per thread. Each block preps its own key chunk inline.
// ---------------------------------------------------------------------------
__global__ void __launch_bounds__(BLK, 4) softmin_kernel(const float* __restrict__ pallet,
                                                         const float* __restrict__ comp) {
    // shared: lane-duplicated key quads: per i, {B2,B2,nx,nx} {ny,ny,nz,nz}
    __shared__ float4 sb[MC * 2];

    const int m0 = blockIdx.y * MC;
    const int mc = min(MC, N_PTS - m0);
    if (threadIdx.x < mc) {
        const int m = m0 + threadIdx.x;
        float bx = comp[3 * m] * LG2E, by = comp[3 * m + 1] * LG2E, bz = comp[3 * m + 2] * LG2E;
        float b2 = bx * bx + by * by + bz * bz;
        float nx = -2.f * bx, ny = -2.f * by, nz = -2.f * bz;
        sb[2 * threadIdx.x]     = make_float4(b2, b2, nx, nx);
        sb[2 * threadIdx.x + 1] = make_float4(ny, ny, nz, nz);
    }

    const int q0 = blockIdx.x * (BLK * Q_PER_THREAD) + threadIdx.x * Q_PER_THREAD;
    float4 a0 = query_quad(pallet, q0);
    float4 a1 = query_quad(pallet, q0 + 1);
    const float2 Ax = make_float2(a0.x, a1.x);
    const float2 Ay = make_float2(a0.y, a1.y);
    const float2 Az = make_float2(a0.z, a1.z);
    const float2 A2 = make_float2(a0.w, a1.w);
    float2 sw = make_float2(0.f, 0.f), cx = sw, cy = sw, cz = sw;

    __syncthreads();

#pragma unroll 4
    for (int i = 0; i < mc; i++) {
        const float4 u4 = sb[2 * i], v4 = sb[2 * i + 1];
        const float2 B2 = make_float2(u4.x, u4.y);
        const float2 nx = make_float2(u4.z, u4.w);
        const float2 ny = make_float2(v4.x, v4.y);
        const float2 nz = make_float2(v4.z, v4.w);
        // s' = |A|^2 + |B|^2 - 2 A.B  (= log2e^2 * |a-b|^2)
        float2 sv = ffma2(nx, Ax, ffma2(ny, Ay, ffma2(nz, Az, fadd2(B2, A2))));
        // u = log2e * dist; w = 2^(-u) = exp(-dist). |.| and neg fold into MUFU.
        float2 w = make_float2(ex2_ap(-sqrt_ap(fabsf(sv.x))),
                               ex2_ap(-sqrt_ap(fabsf(sv.y))));
        sw = fadd2(sw, w);
        cx = ffma2(w, nx, cx);   // accumulates w*(-2*LG2E*bx) etc.
        cy = ffma2(w, ny, cy);
        cz = ffma2(w, nz, cz);
    }

    float4* dst = g_scratch + blockIdx.y * N_PTS + q0;
    dst[0] = make_float4(sw.x, cx.x, cy.x, cz.x);
    dst[1] = make_float4(sw.y, cx.y, cy.y, cz.y);
}

// ---------------------------------------------------------------------------
// Phase 2: per-thread-q reduce. 64 blocks x 128 threads = 8192 threads;
// thread q reads its 37 chunk partials fully unrolled (37-deep MLP,
// lane-coalesced float4s), computes closest + MSE term, warp-reduces,
// one atomicAdd per warp into out.
// ---------------------------------------------------------------------------
#define RBLK 128
__global__ void __launch_bounds__(RBLK) reduce_kernel(const float* __restrict__ pallet,
                                                      float* __restrict__ out) {
    const int q = blockIdx.x * RBLK + threadIdx.x;

    float sw = 0.f, cx = 0.f, cy = 0.f, cz = 0.f;
#pragma unroll
    for (int ch = 0; ch < NCH; ch++) {
        float4 v = g_scratch[ch * N_PTS + q];
        sw += v.x; cx += v.y; cy += v.z; cz += v.w;
    }

    // closest_c = acc_c / (-2 * LG2E * sum_w)   (acc holds w * -2*LG2E*b)
    const float inv = -1.f / (2.f * LG2E * sw);
    float clx = cx * inv, cly = cy * inv, clz = cz * inv;

    float4 a = query_quad(pallet, q);              // LG2E-scaled
    float ex = a.x * ILG2E - clx;
    float ey = a.y * ILG2E - cly;
    float ez = a.z * ILG2E - clz;
    float local = ex * ex + ey * ey + ez * ez;

    for (int off = 16; off > 0; off >>= 1)
        local += __shfl_down_sync(0xFFFFFFFFu, local, off);
    if ((threadIdx.x & 31) == 0)
        atomicAdd(out, local * (1.f / (float)(N_PTS * 3)));
}

// ---------------------------------------------------------------------------
extern "C" void kernel_launch(void* const* d_in, const int* in_sizes, int n_in,
                              void* d_out, int out_size) {
    const float* pallet = (const float*)d_in[0];
    const float* comp   = (const float*)d_in[1];
    float* out = (float*)d_out;

    cudaMemsetAsync(out, 0, sizeof(float));
    softmin_kernel<<<dim3(N_PTS / (BLK * Q_PER_THREAD), NCH), BLK>>>(pallet, comp);
    reduce_kernel<<<N_PTS / RBLK, RBLK>>>(pallet, out);
}